// round 1
// baseline (speedup 1.0000x reference)
#include <cuda_runtime.h>
#include <math.h>

#define BATCH 2
#define TSEQ  1024
#define DIM   1024
#define NH    16
#define HD    64
#define NL    6
#define VOCAB 32000

// ---------------- scratch (device globals; no allocation allowed) ----------
__device__ float g_h   [BATCH * TSEQ * DIM];       // residual stream
__device__ float g_x   [BATCH * TSEQ * DIM];       // LN output
__device__ float g_qkv [BATCH * TSEQ * 3 * DIM];   // qkv projections
__device__ float g_attn[BATCH * TSEQ * DIM];       // attention output
__device__ float g_hl  [BATCH * DIM];              // final-LN of last token

// ---------------- embedding ------------------------------------------------
__global__ void embed_kernel(const int* __restrict__ tokens,
                             const float* __restrict__ te,
                             const float* __restrict__ pe,
                             float* __restrict__ h) {
    int m = blockIdx.x;                 // b*TSEQ + t
    int t = m & (TSEQ - 1);
    int tok = tokens[m];
    for (int d = threadIdx.x; d < DIM; d += 256)
        h[(size_t)m * DIM + d] = te[(size_t)tok * DIM + d] + pe[(size_t)t * DIM + d];
}

// ---------------- block reduce ---------------------------------------------
__device__ __forceinline__ float block_reduce_sum(float v, float* red) {
    #pragma unroll
    for (int o = 16; o > 0; o >>= 1) v += __shfl_down_sync(0xffffffffu, v, o);
    int w = threadIdx.x >> 5;
    if ((threadIdx.x & 31) == 0) red[w] = v;
    __syncthreads();
    if (threadIdx.x == 0) {
        float s = 0.f;
        #pragma unroll
        for (int i = 0; i < 8; i++) s += red[i];
        red[8] = s;
    }
    __syncthreads();
    float r = red[8];
    __syncthreads();
    return r;
}

// ---------------- layernorm (one row per block, 256 threads) ---------------
__global__ void ln_kernel(const float* __restrict__ src,
                          const float* __restrict__ w,
                          const float* __restrict__ bvec,
                          float* __restrict__ dst) {
    __shared__ float red[9];
    const int rowi = blockIdx.x;
    const float* x = src + (size_t)rowi * DIM;
    float v[4];
    #pragma unroll
    for (int i = 0; i < 4; i++) v[i] = x[threadIdx.x + i * 256];
    float mean = block_reduce_sum(v[0] + v[1] + v[2] + v[3], red) * (1.f / DIM);
    float d2 = 0.f;
    #pragma unroll
    for (int i = 0; i < 4; i++) { float t = v[i] - mean; d2 += t * t; }
    float var = block_reduce_sum(d2, red) * (1.f / DIM);
    float inv = rsqrtf(var + 1e-5f);
    #pragma unroll
    for (int i = 0; i < 4; i++) {
        int d = threadIdx.x + i * 256;
        dst[(size_t)rowi * DIM + d] = (v[i] - mean) * inv * w[d] + bvec[d];
    }
}

// final layernorm, only last token of each batch row
__global__ void lnf_kernel(const float* __restrict__ src,
                           const float* __restrict__ w,
                           const float* __restrict__ bvec,
                           float* __restrict__ dst) {
    __shared__ float red[9];
    const int rowi = blockIdx.x * TSEQ + (TSEQ - 1);
    const float* x = src + (size_t)rowi * DIM;
    float v[4];
    #pragma unroll
    for (int i = 0; i < 4; i++) v[i] = x[threadIdx.x + i * 256];
    float mean = block_reduce_sum(v[0] + v[1] + v[2] + v[3], red) * (1.f / DIM);
    float d2 = 0.f;
    #pragma unroll
    for (int i = 0; i < 4; i++) { float t = v[i] - mean; d2 += t * t; }
    float var = block_reduce_sum(d2, red) * (1.f / DIM);
    float inv = rsqrtf(var + 1e-5f);
    #pragma unroll
    for (int i = 0; i < 4; i++) {
        int d = threadIdx.x + i * 256;
        dst[(size_t)blockIdx.x * DIM + d] = (v[i] - mean) * inv * w[d] + bvec[d];
    }
}

// ---------------- SGEMM: C = A @ W + bias (+ optional residual) ------------
// A: (M,K) row-major, W: (K,N) row-major. 128x128x8 tile, 256 threads, 8x8/thread.
template <bool RESID>
__global__ __launch_bounds__(256)
void gemm_kernel(const float* __restrict__ A, const float* __restrict__ Bw,
                 const float* __restrict__ bias, float* __restrict__ C,
                 int M, int N, int K) {
    __shared__ float As[8][128];
    __shared__ float Bs[8][128];
    const int tid  = threadIdx.x;
    const int row0 = blockIdx.y * 128;
    const int col0 = blockIdx.x * 128;
    const int tr   = (tid >> 4) * 8;
    const int tc   = (tid & 15) * 8;
    const int arow = tid >> 1;
    const int akq  = (tid & 1) * 4;
    const int brow = tid >> 5;
    const int bcol = (tid & 31) * 4;

    const float* Ap = A  + (size_t)(row0 + arow) * K + akq;
    const float* Bp = Bw + (size_t)brow * N + col0 + bcol;

    float acc[8][8];
    #pragma unroll
    for (int i = 0; i < 8; i++)
        #pragma unroll
        for (int j = 0; j < 8; j++) acc[i][j] = 0.f;

    for (int kt = 0; kt < K; kt += 8) {
        float4 av = *(const float4*)(Ap + kt);
        float4 bv = *(const float4*)(Bp + (size_t)kt * N);
        As[akq + 0][arow] = av.x;
        As[akq + 1][arow] = av.y;
        As[akq + 2][arow] = av.z;
        As[akq + 3][arow] = av.w;
        *(float4*)&Bs[brow][bcol] = bv;
        __syncthreads();
        #pragma unroll
        for (int k = 0; k < 8; k++) {
            float ar[8], br[8];
            *(float4*)(ar)     = *(const float4*)&As[k][tr];
            *(float4*)(ar + 4) = *(const float4*)&As[k][tr + 4];
            *(float4*)(br)     = *(const float4*)&Bs[k][tc];
            *(float4*)(br + 4) = *(const float4*)&Bs[k][tc + 4];
            #pragma unroll
            for (int i = 0; i < 8; i++)
                #pragma unroll
                for (int j = 0; j < 8; j++)
                    acc[i][j] += ar[i] * br[j];
        }
        __syncthreads();
    }

    #pragma unroll
    for (int i = 0; i < 8; i++) {
        size_t r = (size_t)(row0 + tr + i);
        #pragma unroll
        for (int j = 0; j < 8; j++) {
            int c = col0 + tc + j;
            float v = acc[i][j] + bias[c];
            if (RESID) v += C[r * N + c];
            C[r * N + c] = v;
        }
    }
}

// ---------------- causal flash attention -----------------------------------
// block = (qb, h, b): 64 queries x HD=64, iterate 64-key tiles. 256 threads.
// S and PV phases use 4x4 register blocks; softmax phase is row-oriented.
__global__ __launch_bounds__(256)
void attn_kernel(const float* __restrict__ qkv, float* __restrict__ outp) {
    extern __shared__ float sm[];
    float* Qs = sm;                 // 64*65
    float* Ks = sm + 4160;          // 64*65
    float* Vs = sm + 8320;          // 64*65
    float* Ss = sm + 12480;         // 64*65
    float* mS = sm + 16640;         // 64
    float* lS = mS + 64;            // 64
    float* aS = lS + 64;            // 64

    const int tid  = threadIdx.x;
    const int qb = blockIdx.x, h = blockIdx.y, b = blockIdx.z;
    const int r0   = (tid >> 4) * 4;
    const int c0   = (tid & 15) * 4;
    const int row  = tid >> 2;
    const int quad = tid & 3;

    for (int idx = tid; idx < 64 * 64; idx += 256) {
        int i = idx >> 6, d = idx & 63;
        Qs[i * 65 + d] = qkv[(size_t)(b * TSEQ + qb * 64 + i) * (3 * DIM) + h * HD + d];
    }
    if (tid < 64) { mS[tid] = -1e30f; lS[tid] = 0.f; }

    float O[4][4];
    #pragma unroll
    for (int i = 0; i < 4; i++)
        #pragma unroll
        for (int j = 0; j < 4; j++) O[i][j] = 0.f;

    for (int kb = 0; kb <= qb; kb++) {
        __syncthreads();   // protect Ks/Vs/Ss (prev PV) and mS/lS init
        for (int idx = tid; idx < 64 * 64; idx += 256) {
            int j = idx >> 6, d = idx & 63;
            const float* p = qkv + (size_t)(b * TSEQ + kb * 64 + j) * (3 * DIM) + DIM + h * HD + d;
            Ks[j * 65 + d] = p[0];
            Vs[j * 65 + d] = p[DIM];
        }
        __syncthreads();

        // S = Q K^T (4x4 register block)
        float s[4][4];
        #pragma unroll
        for (int i = 0; i < 4; i++)
            #pragma unroll
            for (int j = 0; j < 4; j++) s[i][j] = 0.f;
        #pragma unroll 8
        for (int d = 0; d < 64; d++) {
            float q[4], k[4];
            #pragma unroll
            for (int i = 0; i < 4; i++) q[i] = Qs[(r0 + i) * 65 + d];
            #pragma unroll
            for (int j = 0; j < 4; j++) k[j] = Ks[(c0 + j) * 65 + d];
            #pragma unroll
            for (int i = 0; i < 4; i++)
                #pragma unroll
                for (int j = 0; j < 4; j++) s[i][j] += q[i] * k[j];
        }
        const bool diag = (kb == qb);
        #pragma unroll
        for (int i = 0; i < 4; i++)
            #pragma unroll
            for (int j = 0; j < 4; j++) {
                float v = s[i][j] * 0.125f;
                if (diag && (c0 + j) > (r0 + i)) v = -1e30f;
                Ss[(r0 + i) * 65 + c0 + j] = v;
            }
        __syncthreads();

        // online softmax, row-oriented (4 lanes per row)
        float mx = -1e30f;
        #pragma unroll
        for (int c = 0; c < 16; c++) mx = fmaxf(mx, Ss[row * 65 + quad * 16 + c]);
        mx = fmaxf(mx, __shfl_xor_sync(0xffffffffu, mx, 1));
        mx = fmaxf(mx, __shfl_xor_sync(0xffffffffu, mx, 2));
        float mold = mS[row];
        float mnew = fmaxf(mold, mx);
        float sum = 0.f;
        #pragma unroll
        for (int c = 0; c < 16; c++) {
            float p = __expf(Ss[row * 65 + quad * 16 + c] - mnew);
            Ss[row * 65 + quad * 16 + c] = p;
            sum += p;
        }
        sum += __shfl_xor_sync(0xffffffffu, sum, 1);
        sum += __shfl_xor_sync(0xffffffffu, sum, 2);
        float alpha = __expf(mold - mnew);
        if (quad == 0) {
            mS[row] = mnew;
            lS[row] = lS[row] * alpha + sum;
            aS[row] = alpha;
        }
        __syncthreads();

        // O = O*alpha + P @ V (4x4 register block)
        #pragma unroll
        for (int i = 0; i < 4; i++) {
            float a = aS[r0 + i];
            #pragma unroll
            for (int j = 0; j < 4; j++) O[i][j] *= a;
        }
        #pragma unroll 4
        for (int jj = 0; jj < 64; jj++) {
            float p[4], v[4];
            #pragma unroll
            for (int i = 0; i < 4; i++) p[i] = Ss[(r0 + i) * 65 + jj];
            #pragma unroll
            for (int j = 0; j < 4; j++) v[j] = Vs[jj * 65 + c0 + j];
            #pragma unroll
            for (int i = 0; i < 4; i++)
                #pragma unroll
                for (int j = 0; j < 4; j++) O[i][j] += p[i] * v[j];
        }
    }
    __syncthreads();  // lS final values visible
    #pragma unroll
    for (int i = 0; i < 4; i++) {
        float inv = 1.f / lS[r0 + i];
        #pragma unroll
        for (int j = 0; j < 4; j++)
            outp[(size_t)(b * TSEQ + qb * 64 + r0 + i) * DIM + h * HD + c0 + j] = O[i][j] * inv;
    }
}

// ---------------- LM head: logits[b,v] = hl[b,:] . head_w[:,v] + head_b[v] -
__global__ __launch_bounds__(256)
void head_kernel(const float* __restrict__ hlast, const float* __restrict__ hw,
                 const float* __restrict__ hb, float* __restrict__ out) {
    __shared__ float sh[2 * DIM];
    for (int i = threadIdx.x; i < 2 * DIM; i += 256) sh[i] = hlast[i];
    __syncthreads();
    int v = blockIdx.x * 256 + threadIdx.x;
    float a0 = hb[v], a1 = a0;
    #pragma unroll 8
    for (int d = 0; d < DIM; d++) {
        float w = hw[(size_t)d * VOCAB + v];
        a0 += sh[d] * w;
        a1 += sh[DIM + d] * w;
    }
    out[v]         = a0;
    out[VOCAB + v] = a1;
}

// ---------------- launch ----------------------------------------------------
extern "C" void kernel_launch(void* const* d_in, const int* in_sizes, int n_in,
                              void* d_out, int out_size) {
    const int*   tokens    = (const int*)  d_in[0];
    const float* tok_embed = (const float*)d_in[1];
    const float* pos_embed = (const float*)d_in[2];
    const float* qkv_w     = (const float*)d_in[3];
    const float* qkv_b     = (const float*)d_in[4];
    const float* out_w     = (const float*)d_in[5];
    const float* out_b     = (const float*)d_in[6];
    const float* ln_w      = (const float*)d_in[7];
    const float* ln_b      = (const float*)d_in[8];
    const float* lnf_w     = (const float*)d_in[9];
    const float* lnf_b     = (const float*)d_in[10];
    const float* head_w    = (const float*)d_in[11];
    const float* head_b    = (const float*)d_in[12];
    float* logits = (float*)d_out;

    float *ph, *px, *pqkv, *pattn, *phl;
    cudaGetSymbolAddress((void**)&ph,    g_h);
    cudaGetSymbolAddress((void**)&px,    g_x);
    cudaGetSymbolAddress((void**)&pqkv,  g_qkv);
    cudaGetSymbolAddress((void**)&pattn, g_attn);
    cudaGetSymbolAddress((void**)&phl,   g_hl);

    const int ATTN_SMEM = (4 * 64 * 65 + 3 * 64) * (int)sizeof(float);  // 67328 B
    cudaFuncSetAttribute(attn_kernel, cudaFuncAttributeMaxDynamicSharedMemorySize, ATTN_SMEM);

    const int M = BATCH * TSEQ;

    embed_kernel<<<M, 256>>>(tokens, tok_embed, pos_embed, ph);

    for (int l = 0; l < NL; l++) {
        ln_kernel<<<M, 256>>>(ph, ln_w + (size_t)l * DIM, ln_b + (size_t)l * DIM, px);
        gemm_kernel<false><<<dim3(3 * DIM / 128, M / 128), 256>>>(
            px, qkv_w + (size_t)l * DIM * 3 * DIM, qkv_b + (size_t)l * 3 * DIM,
            pqkv, M, 3 * DIM, DIM);
        attn_kernel<<<dim3(TSEQ / 64, NH, BATCH), 256, ATTN_SMEM>>>(pqkv, pattn);
        gemm_kernel<true><<<dim3(DIM / 128, M / 128), 256>>>(
            pattn, out_w + (size_t)l * DIM * DIM, out_b + (size_t)l * DIM,
            ph, M, DIM, DIM);
    }

    lnf_kernel<<<BATCH, 256>>>(ph, lnf_w, lnf_b, phl);
    head_kernel<<<VOCAB / 256, 256>>>(phl, head_w, head_b, logits);
}

// round 3
// speedup vs baseline: 1.8728x; 1.8728x over previous
#include <cuda_runtime.h>
#include <cuda_bf16.h>
#include <math.h>
#include <stdint.h>

#define BATCH 2
#define TSEQ  1024
#define DIM   1024
#define NH    16
#define HD    64
#define NL    6
#define VOCAB 32000

// GEMM tiling (mma.sync path — portable to compute_103 virtual arch)
#define BM 128
#define BN 128
#define BK 64
#define PITCH_H     72                    // halfs per smem row (64 + 8 pad)
#define PITCH_B     144                   // bytes per smem row
#define MAT_BYTES   (128 * PITCH_B)       // 18432 B per matrix per stage
#define STAGE_BYTES (4 * MAT_BYTES)       // Ah, Al, Bh, Bl
#define GEMM_SMEM   (2 * STAGE_BYTES)     // 147456 B

// ---------------- scratch (device globals; no allocation allowed) ----------
__device__ float g_h   [BATCH * TSEQ * DIM];          // residual stream
__device__ float g_qkv [BATCH * TSEQ * 3 * DIM];      // qkv projections
__device__ float g_hl  [BATCH * DIM];                 // final-LN of last token

// split-bf16 activations
__device__ __nv_bfloat16 g_xh[BATCH * TSEQ * DIM];
__device__ __nv_bfloat16 g_xl[BATCH * TSEQ * DIM];
__device__ __nv_bfloat16 g_ah[BATCH * TSEQ * DIM];
__device__ __nv_bfloat16 g_al[BATCH * TSEQ * DIM];

// transposed + split weights: [l][n][k] (K-major)
__device__ __nv_bfloat16 g_wqh[NL * 3 * DIM * DIM];
__device__ __nv_bfloat16 g_wql[NL * 3 * DIM * DIM];
__device__ __nv_bfloat16 g_woh[NL * DIM * DIM];
__device__ __nv_bfloat16 g_wol[NL * DIM * DIM];

// ==================== helpers ====================
__device__ __forceinline__ uint32_t smem_u32(const void* p) {
    uint32_t a;
    asm("{ .reg .u64 t; cvta.to.shared.u64 t, %1; cvt.u32.u64 %0, t; }" : "=r"(a) : "l"(p));
    return a;
}
__device__ __forceinline__ void cp16(uint32_t d, const void* g) {
    asm volatile("cp.async.cg.shared.global [%0], [%1], 16;" :: "r"(d), "l"(g));
}
__device__ __forceinline__ void cp_commit() {
    asm volatile("cp.async.commit_group;");
}
__device__ __forceinline__ void ldm4(uint32_t* r, uint32_t addr) {
    asm volatile("ldmatrix.sync.aligned.m8n8.x4.shared.b16 {%0,%1,%2,%3}, [%4];"
        : "=r"(r[0]), "=r"(r[1]), "=r"(r[2]), "=r"(r[3]) : "r"(addr));
}
__device__ __forceinline__ void mma16816(float* c, const uint32_t* a, const uint32_t* b) {
    asm volatile("mma.sync.aligned.m16n8k16.row.col.f32.bf16.bf16.f32 "
        "{%0,%1,%2,%3}, {%4,%5,%6,%7}, {%8,%9}, {%0,%1,%2,%3};"
        : "+f"(c[0]), "+f"(c[1]), "+f"(c[2]), "+f"(c[3])
        : "r"(a[0]), "r"(a[1]), "r"(a[2]), "r"(a[3]), "r"(b[0]), "r"(b[1]));
}
__device__ __forceinline__ void split_bf16(float v, __nv_bfloat16& h, __nv_bfloat16& l) {
    h = __float2bfloat16(v);
    l = __float2bfloat16(v - __bfloat162float(h));
}

// ---------------- embedding ------------------------------------------------
__global__ void embed_kernel(const int* __restrict__ tokens,
                             const float* __restrict__ te,
                             const float* __restrict__ pe,
                             float* __restrict__ h) {
    int m = blockIdx.x;
    int t = m & (TSEQ - 1);
    int tok = tokens[m];
    for (int d = threadIdx.x; d < DIM; d += 256)
        h[(size_t)m * DIM + d] = te[(size_t)tok * DIM + d] + pe[(size_t)t * DIM + d];
}

// ---------------- weight transpose + fp32->bf16 split ----------------------
__global__ void wsplit_kernel(const float* __restrict__ W,
                              __nv_bfloat16* __restrict__ Th,
                              __nv_bfloat16* __restrict__ Tl,
                              int K, int N) {
    __shared__ float t[32][33];
    const int l = blockIdx.z;
    const float* Wl = W + (size_t)l * K * N;
    __nv_bfloat16* Thl = Th + (size_t)l * K * N;
    __nv_bfloat16* Tll = Tl + (size_t)l * K * N;
    int n0 = blockIdx.x * 32, k0 = blockIdx.y * 32;
    #pragma unroll
    for (int i = threadIdx.y; i < 32; i += 8)
        t[i][threadIdx.x] = Wl[(size_t)(k0 + i) * N + n0 + threadIdx.x];
    __syncthreads();
    #pragma unroll
    for (int ni = threadIdx.y; ni < 32; ni += 8) {
        float v = t[threadIdx.x][ni];
        __nv_bfloat16 hh, ll;
        split_bf16(v, hh, ll);
        size_t o = (size_t)(n0 + ni) * K + k0 + threadIdx.x;
        Thl[o] = hh;
        Tll[o] = ll;
    }
}

// ---------------- block reduce ---------------------------------------------
__device__ __forceinline__ float block_reduce_sum(float v, float* red) {
    #pragma unroll
    for (int o = 16; o > 0; o >>= 1) v += __shfl_down_sync(0xffffffffu, v, o);
    int w = threadIdx.x >> 5;
    if ((threadIdx.x & 31) == 0) red[w] = v;
    __syncthreads();
    if (threadIdx.x == 0) {
        float s = 0.f;
        #pragma unroll
        for (int i = 0; i < 8; i++) s += red[i];
        red[8] = s;
    }
    __syncthreads();
    float r = red[8];
    __syncthreads();
    return r;
}

// ---------------- layernorm -> split bf16 ----------------------------------
__global__ void ln_split_kernel(const float* __restrict__ src,
                                const float* __restrict__ w,
                                const float* __restrict__ bvec,
                                __nv_bfloat16* __restrict__ xh,
                                __nv_bfloat16* __restrict__ xl) {
    __shared__ float red[9];
    const int rowi = blockIdx.x;
    const float* x = src + (size_t)rowi * DIM;
    float v[4];
    #pragma unroll
    for (int i = 0; i < 4; i++) v[i] = x[threadIdx.x + i * 256];
    float mean = block_reduce_sum(v[0] + v[1] + v[2] + v[3], red) * (1.f / DIM);
    float d2 = 0.f;
    #pragma unroll
    for (int i = 0; i < 4; i++) { float t = v[i] - mean; d2 += t * t; }
    float var = block_reduce_sum(d2, red) * (1.f / DIM);
    float inv = rsqrtf(var + 1e-5f);
    #pragma unroll
    for (int i = 0; i < 4; i++) {
        int d = threadIdx.x + i * 256;
        float y = (v[i] - mean) * inv * w[d] + bvec[d];
        __nv_bfloat16 hh, ll;
        split_bf16(y, hh, ll);
        xh[(size_t)rowi * DIM + d] = hh;
        xl[(size_t)rowi * DIM + d] = ll;
    }
}

// final layernorm, only last token, fp32 out
__global__ void lnf_kernel(const float* __restrict__ src,
                           const float* __restrict__ w,
                           const float* __restrict__ bvec,
                           float* __restrict__ dst) {
    __shared__ float red[9];
    const int rowi = blockIdx.x * TSEQ + (TSEQ - 1);
    const float* x = src + (size_t)rowi * DIM;
    float v[4];
    #pragma unroll
    for (int i = 0; i < 4; i++) v[i] = x[threadIdx.x + i * 256];
    float mean = block_reduce_sum(v[0] + v[1] + v[2] + v[3], red) * (1.f / DIM);
    float d2 = 0.f;
    #pragma unroll
    for (int i = 0; i < 4; i++) { float t = v[i] - mean; d2 += t * t; }
    float var = block_reduce_sum(d2, red) * (1.f / DIM);
    float inv = rsqrtf(var + 1e-5f);
    #pragma unroll
    for (int i = 0; i < 4; i++) {
        int d = threadIdx.x + i * 256;
        dst[(size_t)blockIdx.x * DIM + d] = (v[i] - mean) * inv * w[d] + bvec[d];
    }
}

// ---------------- HMMA split-bf16 GEMM -------------------------------------
// C = (Ah+Al) @ (Bh+Bl)^T + bias (+residual), fp32 accum.
// A: (M,K=1024) bf16 hi/lo K-major. B: (N,K) bf16 hi/lo K-major.
// 128x128x64 CTA tile, 8 warps (4x2), warp tile 32x64, double-buffered cp.async.
template <bool RESID>
__global__ __launch_bounds__(256, 1)
void mma_gemm(const __nv_bfloat16* __restrict__ Ah, const __nv_bfloat16* __restrict__ Al,
              const __nv_bfloat16* __restrict__ Bh, const __nv_bfloat16* __restrict__ Bl,
              const float* __restrict__ bias, float* __restrict__ C,
              int M, int N) {
    extern __shared__ char smem[];
    const uint32_t sbase = smem_u32(smem);
    const int tid  = threadIdx.x;
    const int lane = tid & 31;
    const int wid  = tid >> 5;
    const int wm   = wid >> 1;            // 0..3
    const int wn   = wid & 1;             // 0..1
    const int row0 = blockIdx.y * BM;
    const int col0 = blockIdx.x * BN;
    const int K    = DIM;
    const int NC   = K / BK;              // 16

    float acc[2][8][4];
    #pragma unroll
    for (int i = 0; i < 2; i++)
        #pragma unroll
        for (int j = 0; j < 8; j++)
            #pragma unroll
            for (int q = 0; q < 4; q++) acc[i][j][q] = 0.f;

    auto load_stage = [&](int s, int c) {
        const uint32_t sb = sbase + s * STAGE_BYTES;
        const int kt = c * BK;
        #pragma unroll
        for (int it = 0; it < 4; it++) {
            int lin = tid + it * 256;             // 0..1023
            int r  = lin >> 3;
            int cq = lin & 7;
            size_t go = (size_t)(row0 + r) * K + kt + cq * 8;
            uint32_t d = sb + r * PITCH_B + cq * 16;
            cp16(d, Ah + go);
            cp16(d + MAT_BYTES, Al + go);
        }
        #pragma unroll
        for (int it = 0; it < 4; it++) {
            int lin = tid + it * 256;
            int r  = lin >> 3;
            int cq = lin & 7;
            size_t go = (size_t)(col0 + r) * K + kt + cq * 8;
            uint32_t d = sb + 2 * MAT_BYTES + r * PITCH_B + cq * 16;
            cp16(d, Bh + go);
            cp16(d + MAT_BYTES, Bl + go);
        }
    };

    load_stage(0, 0); cp_commit();
    load_stage(1, 1); cp_commit();

    const int arow  = wm * 32 + (lane & 15);
    const int acol8 = (lane >> 4) << 3;
    const int brow  = wn * 64 + (lane & 7) + ((lane >> 4) << 3);
    const int bcol8 = ((lane >> 3) & 1) << 3;

    for (int c = 0; c < NC; c++) {
        if (c + 1 < NC) asm volatile("cp.async.wait_group 1;");
        else            asm volatile("cp.async.wait_group 0;");
        __syncthreads();

        const uint32_t ab = sbase + (c & 1) * STAGE_BYTES;
        const uint32_t bb = ab + 2 * MAT_BYTES;
        #pragma unroll
        for (int ks = 0; ks < 4; ks++) {
            const int kc = ks * 16;
            uint32_t ah[2][4], al[2][4];
            #pragma unroll
            for (int mt = 0; mt < 2; mt++) {
                uint32_t ad = ab + (uint32_t)(arow + mt * 16) * PITCH_B + (uint32_t)(kc + acol8) * 2;
                ldm4(ah[mt], ad);
                ldm4(al[mt], ad + MAT_BYTES);
            }
            uint32_t bh[8][2], bl[8][2];
            #pragma unroll
            for (int ng = 0; ng < 4; ng++) {
                uint32_t bd = bb + (uint32_t)(brow + ng * 16) * PITCH_B + (uint32_t)(kc + bcol8) * 2;
                uint32_t t4[4];
                ldm4(t4, bd);
                bh[ng * 2][0] = t4[0]; bh[ng * 2][1] = t4[1];
                bh[ng * 2 + 1][0] = t4[2]; bh[ng * 2 + 1][1] = t4[3];
                ldm4(t4, bd + MAT_BYTES);
                bl[ng * 2][0] = t4[0]; bl[ng * 2][1] = t4[1];
                bl[ng * 2 + 1][0] = t4[2]; bl[ng * 2 + 1][1] = t4[3];
            }
            #pragma unroll
            for (int mt = 0; mt < 2; mt++)
                #pragma unroll
                for (int nt = 0; nt < 8; nt++) {
                    mma16816(acc[mt][nt], ah[mt], bh[nt]);
                    mma16816(acc[mt][nt], ah[mt], bl[nt]);
                    mma16816(acc[mt][nt], al[mt], bh[nt]);
                }
        }
        __syncthreads();
        if (c + 2 < NC) { load_stage(c & 1, c + 2); cp_commit(); }
    }

    // epilogue: fused bias (+residual)
    #pragma unroll
    for (int mt = 0; mt < 2; mt++) {
        #pragma unroll
        for (int nt = 0; nt < 8; nt++) {
            int r  = row0 + wm * 32 + mt * 16 + (lane >> 2);
            int cc = col0 + wn * 64 + nt * 8 + (lane & 3) * 2;
            float b0 = bias[cc], b1 = bias[cc + 1];
            float2* p0 = (float2*)&C[(size_t)r * N + cc];
            float2* p1 = (float2*)&C[(size_t)(r + 8) * N + cc];
            float2 v0 = make_float2(acc[mt][nt][0] + b0, acc[mt][nt][1] + b1);
            float2 v1 = make_float2(acc[mt][nt][2] + b0, acc[mt][nt][3] + b1);
            if (RESID) {
                float2 o0 = *p0, o1 = *p1;
                v0.x += o0.x; v0.y += o0.y;
                v1.x += o1.x; v1.y += o1.y;
            }
            *p0 = v0;
            *p1 = v1;
        }
    }
}

// ---------------- causal flash attention (fp32, split-bf16 output) ---------
__global__ __launch_bounds__(256)
void attn_kernel(const float* __restrict__ qkv,
                 __nv_bfloat16* __restrict__ oh,
                 __nv_bfloat16* __restrict__ ol) {
    extern __shared__ float sm[];
    float* Qs = sm;
    float* Ks = sm + 4160;
    float* Vs = sm + 8320;
    float* Ss = sm + 12480;
    float* mS = sm + 16640;
    float* lS = mS + 64;
    float* aS = lS + 64;

    const int tid  = threadIdx.x;
    const int qb = blockIdx.x, hh = blockIdx.y, b = blockIdx.z;
    const int r0   = (tid >> 4) * 4;
    const int c0   = (tid & 15) * 4;
    const int row  = tid >> 2;
    const int quad = tid & 3;

    for (int idx = tid; idx < 64 * 64; idx += 256) {
        int i = idx >> 6, d = idx & 63;
        Qs[i * 65 + d] = qkv[(size_t)(b * TSEQ + qb * 64 + i) * (3 * DIM) + hh * HD + d];
    }
    if (tid < 64) { mS[tid] = -1e30f; lS[tid] = 0.f; }

    float O[4][4];
    #pragma unroll
    for (int i = 0; i < 4; i++)
        #pragma unroll
        for (int j = 0; j < 4; j++) O[i][j] = 0.f;

    for (int kb = 0; kb <= qb; kb++) {
        __syncthreads();
        for (int idx = tid; idx < 64 * 64; idx += 256) {
            int j = idx >> 6, d = idx & 63;
            const float* p = qkv + (size_t)(b * TSEQ + kb * 64 + j) * (3 * DIM) + DIM + hh * HD + d;
            Ks[j * 65 + d] = p[0];
            Vs[j * 65 + d] = p[DIM];
        }
        __syncthreads();

        float s[4][4];
        #pragma unroll
        for (int i = 0; i < 4; i++)
            #pragma unroll
            for (int j = 0; j < 4; j++) s[i][j] = 0.f;
        #pragma unroll 8
        for (int d = 0; d < 64; d++) {
            float q[4], k[4];
            #pragma unroll
            for (int i = 0; i < 4; i++) q[i] = Qs[(r0 + i) * 65 + d];
            #pragma unroll
            for (int j = 0; j < 4; j++) k[j] = Ks[(c0 + j) * 65 + d];
            #pragma unroll
            for (int i = 0; i < 4; i++)
                #pragma unroll
                for (int j = 0; j < 4; j++) s[i][j] += q[i] * k[j];
        }
        const bool diag = (kb == qb);
        #pragma unroll
        for (int i = 0; i < 4; i++)
            #pragma unroll
            for (int j = 0; j < 4; j++) {
                float v = s[i][j] * 0.125f;
                if (diag && (c0 + j) > (r0 + i)) v = -1e30f;
                Ss[(r0 + i) * 65 + c0 + j] = v;
            }
        __syncthreads();

        float mx = -1e30f;
        #pragma unroll
        for (int c = 0; c < 16; c++) mx = fmaxf(mx, Ss[row * 65 + quad * 16 + c]);
        mx = fmaxf(mx, __shfl_xor_sync(0xffffffffu, mx, 1));
        mx = fmaxf(mx, __shfl_xor_sync(0xffffffffu, mx, 2));
        float mold = mS[row];
        float mnew = fmaxf(mold, mx);
        float sum = 0.f;
        #pragma unroll
        for (int c = 0; c < 16; c++) {
            float p = __expf(Ss[row * 65 + quad * 16 + c] - mnew);
            Ss[row * 65 + quad * 16 + c] = p;
            sum += p;
        }
        sum += __shfl_xor_sync(0xffffffffu, sum, 1);
        sum += __shfl_xor_sync(0xffffffffu, sum, 2);
        float alpha = __expf(mold - mnew);
        if (quad == 0) {
            mS[row] = mnew;
            lS[row] = lS[row] * alpha + sum;
            aS[row] = alpha;
        }
        __syncthreads();

        #pragma unroll
        for (int i = 0; i < 4; i++) {
            float a = aS[r0 + i];
            #pragma unroll
            for (int j = 0; j < 4; j++) O[i][j] *= a;
        }
        #pragma unroll 4
        for (int jj = 0; jj < 64; jj++) {
            float p[4], v[4];
            #pragma unroll
            for (int i = 0; i < 4; i++) p[i] = Ss[(r0 + i) * 65 + jj];
            #pragma unroll
            for (int j = 0; j < 4; j++) v[j] = Vs[jj * 65 + c0 + j];
            #pragma unroll
            for (int i = 0; i < 4; i++)
                #pragma unroll
                for (int j = 0; j < 4; j++) O[i][j] += p[i] * v[j];
        }
    }
    __syncthreads();
    #pragma unroll
    for (int i = 0; i < 4; i++) {
        float inv = 1.f / lS[r0 + i];
        #pragma unroll
        for (int j = 0; j < 4; j++) {
            float o = O[i][j] * inv;
            __nv_bfloat16 vh, vl;
            split_bf16(o, vh, vl);
            size_t idx = (size_t)(b * TSEQ + qb * 64 + r0 + i) * DIM + hh * HD + c0 + j;
            oh[idx] = vh;
            ol[idx] = vl;
        }
    }
}

// ---------------- LM head ---------------------------------------------------
__global__ __launch_bounds__(256)
void head_kernel(const float* __restrict__ hlast, const float* __restrict__ hw,
                 const float* __restrict__ hb, float* __restrict__ out) {
    __shared__ float sh[2 * DIM];
    for (int i = threadIdx.x; i < 2 * DIM; i += 256) sh[i] = hlast[i];
    __syncthreads();
    int v = blockIdx.x * 256 + threadIdx.x;
    float a0 = hb[v], a1 = a0;
    #pragma unroll 8
    for (int d = 0; d < DIM; d++) {
        float w = hw[(size_t)d * VOCAB + v];
        a0 += sh[d] * w;
        a1 += sh[DIM + d] * w;
    }
    out[v]         = a0;
    out[VOCAB + v] = a1;
}

// ---------------- launch ----------------------------------------------------
extern "C" void kernel_launch(void* const* d_in, const int* in_sizes, int n_in,
                              void* d_out, int out_size) {
    const int*   tokens    = (const int*)  d_in[0];
    const float* tok_embed = (const float*)d_in[1];
    const float* pos_embed = (const float*)d_in[2];
    const float* qkv_w     = (const float*)d_in[3];
    const float* qkv_b     = (const float*)d_in[4];
    const float* out_w     = (const float*)d_in[5];
    const float* out_b     = (const float*)d_in[6];
    const float* ln_w      = (const float*)d_in[7];
    const float* ln_b      = (const float*)d_in[8];
    const float* lnf_w     = (const float*)d_in[9];
    const float* lnf_b     = (const float*)d_in[10];
    const float* head_w    = (const float*)d_in[11];
    const float* head_b    = (const float*)d_in[12];
    float* logits = (float*)d_out;

    float *ph, *pqkv, *phl;
    __nv_bfloat16 *pxh, *pxl, *pah, *pal, *pwqh, *pwql, *pwoh, *pwol;
    cudaGetSymbolAddress((void**)&ph,   g_h);
    cudaGetSymbolAddress((void**)&pqkv, g_qkv);
    cudaGetSymbolAddress((void**)&phl,  g_hl);
    cudaGetSymbolAddress((void**)&pxh,  g_xh);
    cudaGetSymbolAddress((void**)&pxl,  g_xl);
    cudaGetSymbolAddress((void**)&pah,  g_ah);
    cudaGetSymbolAddress((void**)&pal,  g_al);
    cudaGetSymbolAddress((void**)&pwqh, g_wqh);
    cudaGetSymbolAddress((void**)&pwql, g_wql);
    cudaGetSymbolAddress((void**)&pwoh, g_woh);
    cudaGetSymbolAddress((void**)&pwol, g_wol);

    const int ATTN_SMEM = (4 * 64 * 65 + 3 * 64) * (int)sizeof(float);
    cudaFuncSetAttribute(attn_kernel, cudaFuncAttributeMaxDynamicSharedMemorySize, ATTN_SMEM);
    cudaFuncSetAttribute(mma_gemm<false>, cudaFuncAttributeMaxDynamicSharedMemorySize, GEMM_SMEM);
    cudaFuncSetAttribute(mma_gemm<true>,  cudaFuncAttributeMaxDynamicSharedMemorySize, GEMM_SMEM);

    const int M = BATCH * TSEQ;

    embed_kernel<<<M, 256>>>(tokens, tok_embed, pos_embed, ph);

    // transpose + split weights
    wsplit_kernel<<<dim3(3 * DIM / 32, DIM / 32, NL), dim3(32, 8)>>>(qkv_w, pwqh, pwql, DIM, 3 * DIM);
    wsplit_kernel<<<dim3(DIM / 32, DIM / 32, NL), dim3(32, 8)>>>(out_w, pwoh, pwol, DIM, DIM);

    for (int l = 0; l < NL; l++) {
        ln_split_kernel<<<M, 256>>>(ph, ln_w + (size_t)l * DIM, ln_b + (size_t)l * DIM, pxh, pxl);
        mma_gemm<false><<<dim3(3 * DIM / BN, M / BM), 256, GEMM_SMEM>>>(
            pxh, pxl,
            pwqh + (size_t)l * 3 * DIM * DIM, pwql + (size_t)l * 3 * DIM * DIM,
            qkv_b + (size_t)l * 3 * DIM, pqkv, M, 3 * DIM);
        attn_kernel<<<dim3(TSEQ / 64, NH, BATCH), 256, ATTN_SMEM>>>(pqkv, pah, pal);
        mma_gemm<true><<<dim3(DIM / BN, M / BM), 256, GEMM_SMEM>>>(
            pah, pal,
            pwoh + (size_t)l * DIM * DIM, pwol + (size_t)l * DIM * DIM,
            out_b + (size_t)l * DIM, ph, M, DIM);
    }

    lnf_kernel<<<BATCH, 256>>>(ph, lnf_w, lnf_b, phl);
    head_kernel<<<VOCAB / 256, 256>>>(phl, head_w, head_b, logits);
}

// round 5
// speedup vs baseline: 3.0665x; 1.6373x over previous
#include <cuda_runtime.h>
#include <cuda_bf16.h>
#include <math.h>
#include <stdint.h>

#define BATCH 2
#define TSEQ  1024
#define DIM   1024
#define NH    16
#define HD    64
#define NL    6
#define VOCAB 32000

// GEMM tiling (mma.sync path — portable to compute_103 virtual arch)
#define BM 128
#define BN 128
#define BK 64
#define PITCH_H     72
#define PITCH_B     144
#define MAT_BYTES   (128 * PITCH_B)
#define STAGE_BYTES (4 * MAT_BYTES)
#define GEMM_SMEM   (2 * STAGE_BYTES)

// attention tiling
#define AT_PITCH 144                       // bytes per 64-half row (64*2 + 16 pad)
#define AT_TILE  (64 * AT_PITCH)           // 9216 B per 64x64 bf16 tile
#define ATTN_SMEM (6 * AT_TILE)            // Qh Ql Kh Kl Vh Vl = 55296 B

// ---------------- scratch (device globals; no allocation allowed) ----------
__device__ float g_h   [BATCH * TSEQ * DIM];
__device__ float g_qkv [BATCH * TSEQ * 3 * DIM];
__device__ float g_hl  [BATCH * DIM];

__device__ __nv_bfloat16 g_xh[BATCH * TSEQ * DIM];
__device__ __nv_bfloat16 g_xl[BATCH * TSEQ * DIM];
__device__ __nv_bfloat16 g_ah[BATCH * TSEQ * DIM];
__device__ __nv_bfloat16 g_al[BATCH * TSEQ * DIM];

__device__ __nv_bfloat16 g_wqh[NL * 3 * DIM * DIM];
__device__ __nv_bfloat16 g_wql[NL * 3 * DIM * DIM];
__device__ __nv_bfloat16 g_woh[NL * DIM * DIM];
__device__ __nv_bfloat16 g_wol[NL * DIM * DIM];

// ==================== helpers ====================
__device__ __forceinline__ uint32_t smem_u32(const void* p) {
    uint32_t a;
    asm("{ .reg .u64 t; cvta.to.shared.u64 t, %1; cvt.u32.u64 %0, t; }" : "=r"(a) : "l"(p));
    return a;
}
__device__ __forceinline__ void cp16(uint32_t d, const void* g) {
    asm volatile("cp.async.cg.shared.global [%0], [%1], 16;" :: "r"(d), "l"(g));
}
__device__ __forceinline__ void cp_commit() {
    asm volatile("cp.async.commit_group;");
}
__device__ __forceinline__ void ldm4(uint32_t* r, uint32_t addr) {
    asm volatile("ldmatrix.sync.aligned.m8n8.x4.shared.b16 {%0,%1,%2,%3}, [%4];"
        : "=r"(r[0]), "=r"(r[1]), "=r"(r[2]), "=r"(r[3]) : "r"(addr));
}
__device__ __forceinline__ void ldm4t(uint32_t* r, uint32_t addr) {
    asm volatile("ldmatrix.sync.aligned.m8n8.x4.trans.shared.b16 {%0,%1,%2,%3}, [%4];"
        : "=r"(r[0]), "=r"(r[1]), "=r"(r[2]), "=r"(r[3]) : "r"(addr));
}
__device__ __forceinline__ void mma16816(float* c, const uint32_t* a, const uint32_t* b) {
    asm volatile("mma.sync.aligned.m16n8k16.row.col.f32.bf16.bf16.f32 "
        "{%0,%1,%2,%3}, {%4,%5,%6,%7}, {%8,%9}, {%0,%1,%2,%3};"
        : "+f"(c[0]), "+f"(c[1]), "+f"(c[2]), "+f"(c[3])
        : "r"(a[0]), "r"(a[1]), "r"(a[2]), "r"(a[3]), "r"(b[0]), "r"(b[1]));
}
__device__ __forceinline__ uint32_t packbf(float lo, float hi) {
    uint32_t r;
    asm("cvt.rn.bf16x2.f32 %0, %1, %2;" : "=r"(r) : "f"(hi), "f"(lo));
    return r;
}
// pack (a,b) into hi-word pair + residual lo-word pair (a = element 0 = low half)
__device__ __forceinline__ void split_pair(float a, float b, uint32_t& hi, uint32_t& lo) {
    float ha = __bfloat162float(__float2bfloat16(a));
    float hb = __bfloat162float(__float2bfloat16(b));
    hi = packbf(a, b);
    lo = packbf(a - ha, b - hb);
}
__device__ __forceinline__ void split_bf16(float v, __nv_bfloat16& h, __nv_bfloat16& l) {
    h = __float2bfloat16(v);
    l = __float2bfloat16(v - __bfloat162float(h));
}

// ---------------- embedding ------------------------------------------------
__global__ void embed_kernel(const int* __restrict__ tokens,
                             const float* __restrict__ te,
                             const float* __restrict__ pe,
                             float* __restrict__ h) {
    int m = blockIdx.x;
    int t = m & (TSEQ - 1);
    int tok = tokens[m];
    for (int d = threadIdx.x; d < DIM; d += 256)
        h[(size_t)m * DIM + d] = te[(size_t)tok * DIM + d] + pe[(size_t)t * DIM + d];
}

// ---------------- weight transpose + fp32->bf16 split ----------------------
__global__ void wsplit_kernel(const float* __restrict__ W,
                              __nv_bfloat16* __restrict__ Th,
                              __nv_bfloat16* __restrict__ Tl,
                              int K, int N) {
    __shared__ float t[32][33];
    const int l = blockIdx.z;
    const float* Wl = W + (size_t)l * K * N;
    __nv_bfloat16* Thl = Th + (size_t)l * K * N;
    __nv_bfloat16* Tll = Tl + (size_t)l * K * N;
    int n0 = blockIdx.x * 32, k0 = blockIdx.y * 32;
    #pragma unroll
    for (int i = threadIdx.y; i < 32; i += 8)
        t[i][threadIdx.x] = Wl[(size_t)(k0 + i) * N + n0 + threadIdx.x];
    __syncthreads();
    #pragma unroll
    for (int ni = threadIdx.y; ni < 32; ni += 8) {
        float v = t[threadIdx.x][ni];
        __nv_bfloat16 hh, ll;
        split_bf16(v, hh, ll);
        size_t o = (size_t)(n0 + ni) * K + k0 + threadIdx.x;
        Thl[o] = hh;
        Tll[o] = ll;
    }
}

// ---------------- block reduce ---------------------------------------------
__device__ __forceinline__ float block_reduce_sum(float v, float* red) {
    #pragma unroll
    for (int o = 16; o > 0; o >>= 1) v += __shfl_down_sync(0xffffffffu, v, o);
    int w = threadIdx.x >> 5;
    if ((threadIdx.x & 31) == 0) red[w] = v;
    __syncthreads();
    if (threadIdx.x == 0) {
        float s = 0.f;
        #pragma unroll
        for (int i = 0; i < 8; i++) s += red[i];
        red[8] = s;
    }
    __syncthreads();
    float r = red[8];
    __syncthreads();
    return r;
}

// ---------------- layernorm -> split bf16 ----------------------------------
__global__ void ln_split_kernel(const float* __restrict__ src,
                                const float* __restrict__ w,
                                const float* __restrict__ bvec,
                                __nv_bfloat16* __restrict__ xh,
                                __nv_bfloat16* __restrict__ xl) {
    __shared__ float red[9];
    const int rowi = blockIdx.x;
    const float* x = src + (size_t)rowi * DIM;
    float v[4];
    #pragma unroll
    for (int i = 0; i < 4; i++) v[i] = x[threadIdx.x + i * 256];
    float mean = block_reduce_sum(v[0] + v[1] + v[2] + v[3], red) * (1.f / DIM);
    float d2 = 0.f;
    #pragma unroll
    for (int i = 0; i < 4; i++) { float t = v[i] - mean; d2 += t * t; }
    float var = block_reduce_sum(d2, red) * (1.f / DIM);
    float inv = rsqrtf(var + 1e-5f);
    #pragma unroll
    for (int i = 0; i < 4; i++) {
        int d = threadIdx.x + i * 256;
        float y = (v[i] - mean) * inv * w[d] + bvec[d];
        __nv_bfloat16 hh, ll;
        split_bf16(y, hh, ll);
        xh[(size_t)rowi * DIM + d] = hh;
        xl[(size_t)rowi * DIM + d] = ll;
    }
}

// final layernorm, only last token, fp32 out
__global__ void lnf_kernel(const float* __restrict__ src,
                           const float* __restrict__ w,
                           const float* __restrict__ bvec,
                           float* __restrict__ dst) {
    __shared__ float red[9];
    const int rowi = blockIdx.x * TSEQ + (TSEQ - 1);
    const float* x = src + (size_t)rowi * DIM;
    float v[4];
    #pragma unroll
    for (int i = 0; i < 4; i++) v[i] = x[threadIdx.x + i * 256];
    float mean = block_reduce_sum(v[0] + v[1] + v[2] + v[3], red) * (1.f / DIM);
    float d2 = 0.f;
    #pragma unroll
    for (int i = 0; i < 4; i++) { float t = v[i] - mean; d2 += t * t; }
    float var = block_reduce_sum(d2, red) * (1.f / DIM);
    float inv = rsqrtf(var + 1e-5f);
    #pragma unroll
    for (int i = 0; i < 4; i++) {
        int d = threadIdx.x + i * 256;
        dst[(size_t)blockIdx.x * DIM + d] = (v[i] - mean) * inv * w[d] + bvec[d];
    }
}

// ---------------- HMMA split-bf16 GEMM -------------------------------------
template <bool RESID>
__global__ __launch_bounds__(256, 1)
void mma_gemm(const __nv_bfloat16* __restrict__ Ah, const __nv_bfloat16* __restrict__ Al,
              const __nv_bfloat16* __restrict__ Bh, const __nv_bfloat16* __restrict__ Bl,
              const float* __restrict__ bias, float* __restrict__ C,
              int M, int N) {
    extern __shared__ char smem[];
    const uint32_t sbase = smem_u32(smem);
    const int tid  = threadIdx.x;
    const int lane = tid & 31;
    const int wid  = tid >> 5;
    const int wm   = wid >> 1;
    const int wn   = wid & 1;
    const int row0 = blockIdx.y * BM;
    const int col0 = blockIdx.x * BN;
    const int K    = DIM;
    const int NC   = K / BK;

    float acc[2][8][4];
    #pragma unroll
    for (int i = 0; i < 2; i++)
        #pragma unroll
        for (int j = 0; j < 8; j++)
            #pragma unroll
            for (int q = 0; q < 4; q++) acc[i][j][q] = 0.f;

    auto load_stage = [&](int s, int c) {
        const uint32_t sb = sbase + s * STAGE_BYTES;
        const int kt = c * BK;
        #pragma unroll
        for (int it = 0; it < 4; it++) {
            int lin = tid + it * 256;
            int r  = lin >> 3;
            int cq = lin & 7;
            size_t go = (size_t)(row0 + r) * K + kt + cq * 8;
            uint32_t d = sb + r * PITCH_B + cq * 16;
            cp16(d, Ah + go);
            cp16(d + MAT_BYTES, Al + go);
        }
        #pragma unroll
        for (int it = 0; it < 4; it++) {
            int lin = tid + it * 256;
            int r  = lin >> 3;
            int cq = lin & 7;
            size_t go = (size_t)(col0 + r) * K + kt + cq * 8;
            uint32_t d = sb + 2 * MAT_BYTES + r * PITCH_B + cq * 16;
            cp16(d, Bh + go);
            cp16(d + MAT_BYTES, Bl + go);
        }
    };

    load_stage(0, 0); cp_commit();
    load_stage(1, 1); cp_commit();

    const int arow  = wm * 32 + (lane & 15);
    const int acol8 = (lane >> 4) << 3;
    const int brow  = wn * 64 + (lane & 7) + ((lane >> 4) << 3);
    const int bcol8 = ((lane >> 3) & 1) << 3;

    for (int c = 0; c < NC; c++) {
        if (c + 1 < NC) asm volatile("cp.async.wait_group 1;");
        else            asm volatile("cp.async.wait_group 0;");
        __syncthreads();

        const uint32_t ab = sbase + (c & 1) * STAGE_BYTES;
        const uint32_t bb = ab + 2 * MAT_BYTES;
        #pragma unroll
        for (int ks = 0; ks < 4; ks++) {
            const int kc = ks * 16;
            uint32_t ah[2][4], al[2][4];
            #pragma unroll
            for (int mt = 0; mt < 2; mt++) {
                uint32_t ad = ab + (uint32_t)(arow + mt * 16) * PITCH_B + (uint32_t)(kc + acol8) * 2;
                ldm4(ah[mt], ad);
                ldm4(al[mt], ad + MAT_BYTES);
            }
            uint32_t bh[8][2], bl[8][2];
            #pragma unroll
            for (int ng = 0; ng < 4; ng++) {
                uint32_t bd = bb + (uint32_t)(brow + ng * 16) * PITCH_B + (uint32_t)(kc + bcol8) * 2;
                uint32_t t4[4];
                ldm4(t4, bd);
                bh[ng * 2][0] = t4[0]; bh[ng * 2][1] = t4[1];
                bh[ng * 2 + 1][0] = t4[2]; bh[ng * 2 + 1][1] = t4[3];
                ldm4(t4, bd + MAT_BYTES);
                bl[ng * 2][0] = t4[0]; bl[ng * 2][1] = t4[1];
                bl[ng * 2 + 1][0] = t4[2]; bl[ng * 2 + 1][1] = t4[3];
            }
            #pragma unroll
            for (int mt = 0; mt < 2; mt++)
                #pragma unroll
                for (int nt = 0; nt < 8; nt++) {
                    mma16816(acc[mt][nt], ah[mt], bh[nt]);
                    mma16816(acc[mt][nt], ah[mt], bl[nt]);
                    mma16816(acc[mt][nt], al[mt], bh[nt]);
                }
        }
        __syncthreads();
        if (c + 2 < NC) { load_stage(c & 1, c + 2); cp_commit(); }
    }

    #pragma unroll
    for (int mt = 0; mt < 2; mt++) {
        #pragma unroll
        for (int nt = 0; nt < 8; nt++) {
            int r  = row0 + wm * 32 + mt * 16 + (lane >> 2);
            int cc = col0 + wn * 64 + nt * 8 + (lane & 3) * 2;
            float b0 = bias[cc], b1 = bias[cc + 1];
            float2* p0 = (float2*)&C[(size_t)r * N + cc];
            float2* p1 = (float2*)&C[(size_t)(r + 8) * N + cc];
            float2 v0 = make_float2(acc[mt][nt][0] + b0, acc[mt][nt][1] + b1);
            float2 v1 = make_float2(acc[mt][nt][2] + b0, acc[mt][nt][3] + b1);
            if (RESID) {
                float2 o0 = *p0, o1 = *p1;
                v0.x += o0.x; v0.y += o0.y;
                v1.x += o1.x; v1.y += o1.y;
            }
            *p0 = v0;
            *p1 = v1;
        }
    }
}

// ---------------- HMMA causal flash attention ------------------------------
// CTA: 64 queries x HD=64, 128 threads (4 warps, 16 query rows each).
// Split-bf16 (3-product) for both QK^T and PV; softmax in registers;
// P A-fragments built directly from S accumulators (FA2 layout identity).
__global__ __launch_bounds__(128)
void attn_mma_kernel(const float* __restrict__ qkv,
                     __nv_bfloat16* __restrict__ oh,
                     __nv_bfloat16* __restrict__ ol) {
    extern __shared__ char asmem[];
    const uint32_t sb = smem_u32(asmem);
    const uint32_t sQh = sb;
    const uint32_t sKh = sb + 2 * AT_TILE;
    const uint32_t sVh = sb + 4 * AT_TILE;
    const int tid = threadIdx.x, lane = tid & 31, w = tid >> 5;
    const int qb = (int)(gridDim.x - 1) - (int)blockIdx.x;   // heavy blocks first
    const int hh = blockIdx.y, b = blockIdx.z;

    // ---- load Q tile, fold 1/8 scale, split to bf16 hi/lo ----
    #pragma unroll
    for (int i = 0; i < 8; i++) {
        int lin = tid + i * 128, r = lin >> 4, c4 = lin & 15;
        float4 q = *(const float4*)&qkv[(size_t)(b * TSEQ + qb * 64 + r) * (3 * DIM) + hh * HD + c4 * 4];
        q.x *= 0.125f; q.y *= 0.125f; q.z *= 0.125f; q.w *= 0.125f;
        uint32_t h0, l0, h1, l1;
        split_pair(q.x, q.y, h0, l0);
        split_pair(q.z, q.w, h1, l1);
        int off = r * AT_PITCH + c4 * 8;
        *(uint2*)(asmem + off)           = make_uint2(h0, h1);
        *(uint2*)(asmem + AT_TILE + off) = make_uint2(l0, l1);
    }
    __syncthreads();

    // ---- Q fragments (loop-invariant) ----
    uint32_t qh[4][4], ql[4][4];
    {
        int r  = (w << 4) + (lane & 15);
        int c8 = (lane >> 4) << 3;
        #pragma unroll
        for (int kc = 0; kc < 4; kc++) {
            uint32_t ad = sQh + (uint32_t)r * AT_PITCH + (uint32_t)(kc * 16 + c8) * 2;
            ldm4(qh[kc], ad);
            ldm4(ql[kc], ad + AT_TILE);
        }
    }

    float o[8][4];
    #pragma unroll
    for (int nt = 0; nt < 8; nt++)
        #pragma unroll
        for (int q = 0; q < 4; q++) o[nt][q] = 0.f;
    float mrow[2] = {-1e30f, -1e30f};
    float lrow[2] = {0.f, 0.f};

    // lane mappings (derived from ldmatrix x4 lane->matrix tiling):
    // K non-trans ([n][k] storage): matrices tile n first within k-halves
    const uint32_t krow_s = (uint32_t)((lane & 7) + ((lane >> 4) << 3));  // n-row
    const uint32_t kcol_s = (uint32_t)(((lane >> 3) & 1) << 3);           // k-col offset
    // V trans ([k][n] storage): matrices tile k-halves first within n-tiles
    const uint32_t krow_v = (uint32_t)((lane & 7) + (((lane >> 3) & 1) << 3)); // k-row
    const uint32_t ncol_v = (uint32_t)((lane >> 4) << 3);                      // n-col offset

    for (int kb = 0; kb <= qb; kb++) {
        __syncthreads();   // previous iteration's K/V reads complete
        #pragma unroll
        for (int i = 0; i < 8; i++) {
            int lin = tid + i * 128, r = lin >> 4, c4 = lin & 15;
            size_t gb = (size_t)(b * TSEQ + kb * 64 + r) * (3 * DIM) + DIM + hh * HD + c4 * 4;
            float4 kv = *(const float4*)&qkv[gb];
            float4 vv = *(const float4*)&qkv[gb + DIM];
            uint32_t h0, l0, h1, l1;
            int off = r * AT_PITCH + c4 * 8;
            split_pair(kv.x, kv.y, h0, l0);
            split_pair(kv.z, kv.w, h1, l1);
            *(uint2*)(asmem + 2 * AT_TILE + off) = make_uint2(h0, h1);
            *(uint2*)(asmem + 3 * AT_TILE + off) = make_uint2(l0, l1);
            split_pair(vv.x, vv.y, h0, l0);
            split_pair(vv.z, vv.w, h1, l1);
            *(uint2*)(asmem + 4 * AT_TILE + off) = make_uint2(h0, h1);
            *(uint2*)(asmem + 5 * AT_TILE + off) = make_uint2(l0, l1);
        }
        __syncthreads();

        // ---- S = Q K^T ----
        float s[8][4];
        #pragma unroll
        for (int nt = 0; nt < 8; nt++)
            #pragma unroll
            for (int q = 0; q < 4; q++) s[nt][q] = 0.f;
        #pragma unroll
        for (int kc = 0; kc < 4; kc++) {
            #pragma unroll
            for (int ng = 0; ng < 4; ng++) {
                uint32_t th[4], tl[4];
                uint32_t ad = sKh + (ng * 16 + krow_s) * AT_PITCH + (kc * 16 + kcol_s) * 2;
                ldm4(th, ad);
                ldm4(tl, ad + AT_TILE);
                mma16816(s[2 * ng],     qh[kc], th);
                mma16816(s[2 * ng],     ql[kc], th);
                mma16816(s[2 * ng],     qh[kc], tl);
                mma16816(s[2 * ng + 1], qh[kc], th + 2);
                mma16816(s[2 * ng + 1], ql[kc], th + 2);
                mma16816(s[2 * ng + 1], qh[kc], tl + 2);
            }
        }

        // ---- causal mask (diagonal tile only) ----
        if (kb == qb) {
            int rl = (w << 4) + (lane >> 2);
            #pragma unroll
            for (int nt = 0; nt < 8; nt++) {
                int cl = nt * 8 + (lane & 3) * 2;
                if (cl     > rl)     s[nt][0] = -1e30f;
                if (cl + 1 > rl)     s[nt][1] = -1e30f;
                if (cl     > rl + 8) s[nt][2] = -1e30f;
                if (cl + 1 > rl + 8) s[nt][3] = -1e30f;
            }
        }

        // ---- online softmax (two rows per thread) ----
        #pragma unroll
        for (int hf = 0; hf < 2; hf++) {
            float mx = -1e30f;
            #pragma unroll
            for (int nt = 0; nt < 8; nt++)
                mx = fmaxf(mx, fmaxf(s[nt][2 * hf], s[nt][2 * hf + 1]));
            mx = fmaxf(mx, __shfl_xor_sync(0xffffffffu, mx, 1));
            mx = fmaxf(mx, __shfl_xor_sync(0xffffffffu, mx, 2));
            float mnew  = fmaxf(mrow[hf], mx);
            float alpha = __expf(mrow[hf] - mnew);
            mrow[hf] = mnew;
            float sum = 0.f;
            #pragma unroll
            for (int nt = 0; nt < 8; nt++) {
                float p0 = __expf(s[nt][2 * hf]     - mnew);
                float p1 = __expf(s[nt][2 * hf + 1] - mnew);
                s[nt][2 * hf] = p0; s[nt][2 * hf + 1] = p1;
                sum += p0 + p1;
                o[nt][2 * hf] *= alpha; o[nt][2 * hf + 1] *= alpha;
            }
            sum += __shfl_xor_sync(0xffffffffu, sum, 1);
            sum += __shfl_xor_sync(0xffffffffu, sum, 2);
            lrow[hf] = lrow[hf] * alpha + sum;
        }

        // ---- O += P @ V ----
        #pragma unroll
        for (int kt = 0; kt < 4; kt++) {
            uint32_t aPh[4], aPl[4];
            split_pair(s[2 * kt][0],     s[2 * kt][1],     aPh[0], aPl[0]);
            split_pair(s[2 * kt][2],     s[2 * kt][3],     aPh[1], aPl[1]);
            split_pair(s[2 * kt + 1][0], s[2 * kt + 1][1], aPh[2], aPl[2]);
            split_pair(s[2 * kt + 1][2], s[2 * kt + 1][3], aPh[3], aPl[3]);
            #pragma unroll
            for (int no = 0; no < 4; no++) {
                uint32_t tv[4];
                uint32_t ad = sVh + (kt * 16 + krow_v) * AT_PITCH + (no * 16 + ncol_v) * 2;
                ldm4t(tv, ad);
                mma16816(o[2 * no],     aPh, tv);
                mma16816(o[2 * no],     aPl, tv);
                mma16816(o[2 * no + 1], aPh, tv + 2);
                mma16816(o[2 * no + 1], aPl, tv + 2);
                ldm4t(tv, ad + AT_TILE);
                mma16816(o[2 * no],     aPh, tv);
                mma16816(o[2 * no + 1], aPh, tv + 2);
            }
        }
    }

    // ---- normalize + split-bf16 output ----
    #pragma unroll
    for (int hf = 0; hf < 2; hf++) {
        float inv = 1.f / lrow[hf];
        int r = qb * 64 + (w << 4) + (lane >> 2) + hf * 8;
        size_t base = (size_t)(b * TSEQ + r) * DIM + hh * HD;
        #pragma unroll
        for (int nt = 0; nt < 8; nt++) {
            int c = nt * 8 + (lane & 3) * 2;
            float v0 = o[nt][2 * hf] * inv, v1 = o[nt][2 * hf + 1] * inv;
            __nv_bfloat16 h0, l0, h1, l1;
            split_bf16(v0, h0, l0);
            split_bf16(v1, h1, l1);
            *(__nv_bfloat162*)&oh[base + c] = __nv_bfloat162(h0, h1);
            *(__nv_bfloat162*)&ol[base + c] = __nv_bfloat162(l0, l1);
        }
    }
}

// ---------------- LM head ---------------------------------------------------
__global__ __launch_bounds__(256)
void head_kernel(const float* __restrict__ hlast, const float* __restrict__ hw,
                 const float* __restrict__ hb, float* __restrict__ out) {
    __shared__ float sh[2 * DIM];
    for (int i = threadIdx.x; i < 2 * DIM; i += 256) sh[i] = hlast[i];
    __syncthreads();
    int v = blockIdx.x * 256 + threadIdx.x;
    float a0 = hb[v], a1 = a0;
    #pragma unroll 8
    for (int d = 0; d < DIM; d++) {
        float w = hw[(size_t)d * VOCAB + v];
        a0 += sh[d] * w;
        a1 += sh[DIM + d] * w;
    }
    out[v]         = a0;
    out[VOCAB + v] = a1;
}

// ---------------- launch ----------------------------------------------------
extern "C" void kernel_launch(void* const* d_in, const int* in_sizes, int n_in,
                              void* d_out, int out_size) {
    const int*   tokens    = (const int*)  d_in[0];
    const float* tok_embed = (const float*)d_in[1];
    const float* pos_embed = (const float*)d_in[2];
    const float* qkv_w     = (const float*)d_in[3];
    const float* qkv_b     = (const float*)d_in[4];
    const float* out_w     = (const float*)d_in[5];
    const float* out_b     = (const float*)d_in[6];
    const float* ln_w      = (const float*)d_in[7];
    const float* ln_b      = (const float*)d_in[8];
    const float* lnf_w     = (const float*)d_in[9];
    const float* lnf_b     = (const float*)d_in[10];
    const float* head_w    = (const float*)d_in[11];
    const float* head_b    = (const float*)d_in[12];
    float* logits = (float*)d_out;

    float *ph, *pqkv, *phl;
    __nv_bfloat16 *pxh, *pxl, *pah, *pal, *pwqh, *pwql, *pwoh, *pwol;
    cudaGetSymbolAddress((void**)&ph,   g_h);
    cudaGetSymbolAddress((void**)&pqkv, g_qkv);
    cudaGetSymbolAddress((void**)&phl,  g_hl);
    cudaGetSymbolAddress((void**)&pxh,  g_xh);
    cudaGetSymbolAddress((void**)&pxl,  g_xl);
    cudaGetSymbolAddress((void**)&pah,  g_ah);
    cudaGetSymbolAddress((void**)&pal,  g_al);
    cudaGetSymbolAddress((void**)&pwqh, g_wqh);
    cudaGetSymbolAddress((void**)&pwql, g_wql);
    cudaGetSymbolAddress((void**)&pwoh, g_woh);
    cudaGetSymbolAddress((void**)&pwol, g_wol);

    cudaFuncSetAttribute(attn_mma_kernel, cudaFuncAttributeMaxDynamicSharedMemorySize, ATTN_SMEM);
    cudaFuncSetAttribute(mma_gemm<false>, cudaFuncAttributeMaxDynamicSharedMemorySize, GEMM_SMEM);
    cudaFuncSetAttribute(mma_gemm<true>,  cudaFuncAttributeMaxDynamicSharedMemorySize, GEMM_SMEM);

    const int M = BATCH * TSEQ;

    embed_kernel<<<M, 256>>>(tokens, tok_embed, pos_embed, ph);

    wsplit_kernel<<<dim3(3 * DIM / 32, DIM / 32, NL), dim3(32, 8)>>>(qkv_w, pwqh, pwql, DIM, 3 * DIM);
    wsplit_kernel<<<dim3(DIM / 32, DIM / 32, NL), dim3(32, 8)>>>(out_w, pwoh, pwol, DIM, DIM);

    for (int l = 0; l < NL; l++) {
        ln_split_kernel<<<M, 256>>>(ph, ln_w + (size_t)l * DIM, ln_b + (size_t)l * DIM, pxh, pxl);
        mma_gemm<false><<<dim3(3 * DIM / BN, M / BM), 256, GEMM_SMEM>>>(
            pxh, pxl,
            pwqh + (size_t)l * 3 * DIM * DIM, pwql + (size_t)l * 3 * DIM * DIM,
            qkv_b + (size_t)l * 3 * DIM, pqkv, M, 3 * DIM);
        attn_mma_kernel<<<dim3(TSEQ / 64, NH, BATCH), 128, ATTN_SMEM>>>(pqkv, pah, pal);
        mma_gemm<true><<<dim3(DIM / BN, M / BM), 256, GEMM_SMEM>>>(
            pah, pal,
            pwoh + (size_t)l * DIM * DIM, pwol + (size_t)l * DIM * DIM,
            out_b + (size_t)l * DIM, ph, M, DIM);
    }

    lnf_kernel<<<BATCH, 256>>>(ph, lnf_w, lnf_b, phl);
    head_kernel<<<VOCAB / 256, 256>>>(phl, head_w, head_b, logits);
}